// round 3
// baseline (speedup 1.0000x reference)
#include <cuda_runtime.h>

#define D    128
#define SEQ  4096
#define NQ   64
#define CH   16

// One CTA per (b, q). 256 threads.
//   Phase 1: scores s[n] = scale * dot(q, K[n])   (warp-per-row)
//   Phase 2: softmax over n (block reductions in smem)
//   Phase 3: acc[v][k] = sum_n (a[n]*V[n,v]) * K[n,k]   (8x8 register tiles)
//            o[v] = sum_n a[n]*V[n,v], w[k] = sum_n a[n]*K[n,k] as staging partials
//   Epilogue: J = scale * (acc - o[v]*w[k])
__global__ __launch_bounds__(256, 2)
void jac_kernel(const float* __restrict__ Q, const float* __restrict__ K,
                const float* __restrict__ V, float* __restrict__ out)
{
    __shared__ float q_sm[D];
    __shared__ float a_sm[SEQ];
    __shared__ float wv_sm[CH][D];     // a[n] * V rows (staged)
    __shared__ float kk_sm[CH][D];     // raw K rows (staged)
    __shared__ float opart_sm[8][D];   // o column-sum partials
    __shared__ float wpart_sm[8][D];   // w column-sum partials
    __shared__ float o_sm[D];
    __shared__ float w_sm[D];
    __shared__ float red_sm[8];

    const int tid  = threadIdx.x;
    const int lane = tid & 31;
    const int wid  = tid >> 5;
    const int q    = blockIdx.x;
    const int b    = blockIdx.y;

    const float* __restrict__ Kb = K + (size_t)b * SEQ * D;
    const float* __restrict__ Vb = V + (size_t)b * SEQ * D;
    const float* __restrict__ Qp = Q + ((size_t)b * NQ + q) * D;

    if (tid < 32) ((float4*)q_sm)[tid] = ((const float4*)Qp)[tid];
    __syncthreads();

    const float scale = 0.088388347648318447f;  // 1/sqrt(128)

    // ---------------- Phase 1: scores ----------------
    float4 qf = ((const float4*)q_sm)[lane];
    float lmax = -1e30f;
    for (int n = wid; n < SEQ; n += 8) {
        float4 kf = ((const float4*)(Kb + (size_t)n * D))[lane];
        float dp = qf.x*kf.x + qf.y*kf.y + qf.z*kf.z + qf.w*kf.w;
        dp += __shfl_xor_sync(0xffffffffu, dp, 16);
        dp += __shfl_xor_sync(0xffffffffu, dp, 8);
        dp += __shfl_xor_sync(0xffffffffu, dp, 4);
        dp += __shfl_xor_sync(0xffffffffu, dp, 2);
        dp += __shfl_xor_sync(0xffffffffu, dp, 1);
        dp *= scale;
        if (lane == 0) a_sm[n] = dp;
        lmax = fmaxf(lmax, dp);          // identical across lanes after reduce
    }
    if (lane == 0) red_sm[wid] = lmax;
    __syncthreads();
    float gmax = red_sm[0];
    #pragma unroll
    for (int i = 1; i < 8; i++) gmax = fmaxf(gmax, red_sm[i]);
    __syncthreads();   // everyone done reading red_sm before it's reused

    // ---------------- Phase 2: softmax ----------------
    float lsum = 0.f;
    for (int n = tid; n < SEQ; n += 256) {
        float e = __expf(a_sm[n] - gmax);
        a_sm[n] = e;
        lsum += e;
    }
    lsum += __shfl_xor_sync(0xffffffffu, lsum, 16);
    lsum += __shfl_xor_sync(0xffffffffu, lsum, 8);
    lsum += __shfl_xor_sync(0xffffffffu, lsum, 4);
    lsum += __shfl_xor_sync(0xffffffffu, lsum, 2);
    lsum += __shfl_xor_sync(0xffffffffu, lsum, 1);
    if (lane == 0) red_sm[wid] = lsum;
    __syncthreads();
    float gsum = 0.f;
    #pragma unroll
    for (int i = 0; i < 8; i++) gsum += red_sm[i];
    const float inv = 1.0f / gsum;
    for (int n = tid; n < SEQ; n += 256) a_sm[n] *= inv;
    // (first __syncthreads of the main loop fences these writes)

    // ---------------- Phase 3: main accumulation ----------------
    float acc[8][8];
    #pragma unroll
    for (int i = 0; i < 8; i++)
        #pragma unroll
        for (int j = 0; j < 8; j++) acc[i][j] = 0.f;

    float4 po = make_float4(0.f, 0.f, 0.f, 0.f);   // o partial (this thread's 4 cols)
    float4 pw = make_float4(0.f, 0.f, 0.f, 0.f);   // w partial

    const int r0 = tid >> 5;   // staging row 0..7 (and r0+8)
    const int c0 = tid & 31;   // staging float4 column
    const int tv = tid >> 4;   // output v-tile 0..15
    const int tk = tid & 15;   // output k-tile 0..15

    for (int n0 = 0; n0 < SEQ; n0 += CH) {
        __syncthreads();   // previous tile consumed (and a_sm normalized on iter 0)
        float a0 = a_sm[n0 + r0];
        float a1 = a_sm[n0 + r0 + 8];
        float4 v0 = ((const float4*)(Vb + (size_t)(n0 + r0    ) * D))[c0];
        float4 v1 = ((const float4*)(Vb + (size_t)(n0 + r0 + 8) * D))[c0];
        float4 k0 = ((const float4*)(Kb + (size_t)(n0 + r0    ) * D))[c0];
        float4 k1 = ((const float4*)(Kb + (size_t)(n0 + r0 + 8) * D))[c0];
        float4 w0 = make_float4(a0*v0.x, a0*v0.y, a0*v0.z, a0*v0.w);
        float4 w1 = make_float4(a1*v1.x, a1*v1.y, a1*v1.z, a1*v1.w);
        ((float4*)wv_sm[r0    ])[c0] = w0;
        ((float4*)wv_sm[r0 + 8])[c0] = w1;
        ((float4*)kk_sm[r0    ])[c0] = k0;
        ((float4*)kk_sm[r0 + 8])[c0] = k1;
        po.x += w0.x + w1.x;  po.y += w0.y + w1.y;
        po.z += w0.z + w1.z;  po.w += w0.w + w1.w;
        pw.x += a0*k0.x + a1*k1.x;  pw.y += a0*k0.y + a1*k1.y;
        pw.z += a0*k0.z + a1*k1.z;  pw.w += a0*k0.w + a1*k1.w;
        __syncthreads();

        #pragma unroll
        for (int r = 0; r < CH; r++) {
            float4 wa = *((const float4*)&wv_sm[r][tv*8]);
            float4 wb = *((const float4*)&wv_sm[r][tv*8 + 4]);
            float4 ka = *((const float4*)&kk_sm[r][tk*8]);
            float4 kb = *((const float4*)&kk_sm[r][tk*8 + 4]);
            float wv8[8] = {wa.x, wa.y, wa.z, wa.w, wb.x, wb.y, wb.z, wb.w};
            float kk8[8] = {ka.x, ka.y, ka.z, ka.w, kb.x, kb.y, kb.z, kb.w};
            #pragma unroll
            for (int i = 0; i < 8; i++)
                #pragma unroll
                for (int j = 0; j < 8; j++)
                    acc[i][j] += wv8[i] * kk8[j];
        }
    }

    // ---------------- reduce o / w partials ----------------
    ((float4*)opart_sm[r0])[c0] = po;
    ((float4*)wpart_sm[r0])[c0] = pw;
    __syncthreads();
    if (tid < D) {
        float s = 0.f;
        #pragma unroll
        for (int g = 0; g < 8; g++) s += opart_sm[g][tid];
        o_sm[tid] = s;
    } else {
        int t = tid - D;
        float s = 0.f;
        #pragma unroll
        for (int g = 0; g < 8; g++) s += wpart_sm[g][t];
        w_sm[t] = s;
    }
    __syncthreads();

    // ---------------- epilogue ----------------
    float ov[8], wk[8];
    #pragma unroll
    for (int i = 0; i < 8; i++) ov[i] = o_sm[tv*8 + i];
    #pragma unroll
    for (int j = 0; j < 8; j++) wk[j] = w_sm[tk*8 + j];

    float* outp = out + ((size_t)b * NQ + q) * D * D;
    #pragma unroll
    for (int i = 0; i < 8; i++) {
        int v = tv*8 + i;
        float vals[8];
        #pragma unroll
        for (int j = 0; j < 8; j++)
            vals[j] = scale * (acc[i][j] - ov[i] * wk[j]);
        float4 x0 = make_float4(vals[0], vals[1], vals[2], vals[3]);
        float4 x1 = make_float4(vals[4], vals[5], vals[6], vals[7]);
        float* rowp = outp + (size_t)v * D + tk*8;
        ((float4*)rowp)[0] = x0;
        ((float4*)rowp)[1] = x1;
    }
}

extern "C" void kernel_launch(void* const* d_in, const int* in_sizes, int n_in,
                              void* d_out, int out_size) {
    const float* Q = (const float*)d_in[0];
    const float* K = (const float*)d_in[1];
    const float* V = (const float*)d_in[2];
    float* out = (float*)d_out;
    int batch = in_sizes[0] / (NQ * D);
    dim3 grid(NQ, batch);
    jac_kernel<<<grid, 256>>>(Q, K, V, out);
}